// round 13
// baseline (speedup 1.0000x reference)
#include <cuda_runtime.h>
#include <cuda_bf16.h>
#include <cstdint>

#define NN  50000
#define NE  800000
#define NNP 50112              // 174 * 288, padded row count

__device__ int      g_cnt[NN];
__device__ int      g_off[NN + 1];
__device__ int      g_cur[NN];
__device__ int      g_csr_row[NE];
__device__ float    g_dinv[NN];
__device__ float    g_H[NN * 128];         // fp32 linear output of current layer
__device__ uint32_t g_hidden[NNP * 128];   // relu(layer1) as tf32, swizzled
__device__ uint32_t g_Xtf[NNP * 128];      // x as tf32, swizzled
__device__ uint32_t g_Wtf1[128 * 128];     // W1 tf32, permuted+swizzled
__device__ uint32_t g_Wtf23[128 * 128];    // [W2|W3] tf32, permuted+swizzled

__device__ __forceinline__ uint32_t f2tf32(float f) {
    uint32_t r;
    asm("cvt.rna.tf32.f32 %0, %1;" : "=r"(r) : "f"(f));
    return r;
}

// ---------------------------------------------------------------------------
// prep (fused): cvtX (6250 blk) | packW (32 blk) | hist (3125 blk)
// g_cnt zero at every launch: zero-init at load, re-zeroed by scan_kernel.
// X swizzle: physical col = col ^ ((row&7)<<2)   (uint4 granularity preserved)
// W layout:  physical col = ((n&7)*16 + (n>>3)) ^ ((k&7)<<2)
// ---------------------------------------------------------------------------
#define PREP_CVT_BLOCKS 6250
#define PREP_W_BLOCKS   32
#define PREP_H_BLOCKS   3125
#define PREP_BLOCKS (PREP_CVT_BLOCKS + PREP_W_BLOCKS + PREP_H_BLOCKS)

__global__ void prep_kernel(const float* __restrict__ x,
                            const float* __restrict__ W1,
                            const float* __restrict__ W2,
                            const float* __restrict__ W3,
                            const int* __restrict__ ei) {
    int b = blockIdx.x;
    int t = threadIdx.x;
    if (b < PREP_CVT_BLOCKS) {
        int i = b * 256 + t;                 // uint4 index over NN*32
        if (i < NN * 32) {
            int row = i >> 5;
            int c4  = (i & 31) << 2;
            float4 v = ((const float4*)x)[i];
            uint4 u;
            u.x = f2tf32(v.x); u.y = f2tf32(v.y);
            u.z = f2tf32(v.z); u.w = f2tf32(v.w);
            int pc4 = c4 ^ ((row & 7) << 2);
            ((uint4*)g_Xtf)[row * 32 + (pc4 >> 2)] = u;
        }
    } else if (b < PREP_CVT_BLOCKS + PREP_W_BLOCKS) {
        int j = (b - PREP_CVT_BLOCKS) * 256 + t;   // float4 idx over W1 then W23
        int k, c4;
        float4 v;
        uint32_t* dst;
        if (j < 4096) {
            k = j >> 5; c4 = (j & 31) << 2;
            v = ((const float4*)W1)[j];
            dst = g_Wtf1;
        } else {
            int jj = j - 4096;
            k = jj >> 5; c4 = (jj & 31) << 2;
            if (c4 < 64) v = *(const float4*)(W2 + k * 64 + c4);
            else         v = *(const float4*)(W3 + k * 64 + (c4 - 64));
            dst = g_Wtf23;
        }
        float vv[4] = {v.x, v.y, v.z, v.w};
        int swz = (k & 7) << 2;
#pragma unroll
        for (int u = 0; u < 4; u++) {
            int n = c4 + u;
            int pcol = ((n & 7) * 16 + (n >> 3)) ^ swz;
            dst[k * 128 + pcol] = f2tf32(vv[u]);
        }
    } else {
        int e = (b - PREP_CVT_BLOCKS - PREP_W_BLOCKS) * 256 + t;
        if (e < NE) atomicAdd(&g_cnt[ei[NE + e]], 1);
    }
}

// ---------------------------------------------------------------------------
// scan: exclusive scan of g_cnt -> off/cur, dinv; re-zeroes g_cnt for the
// next launch (restores the load-time invariant; deterministic per call).
// ---------------------------------------------------------------------------
__global__ void scan_kernel() {
    __shared__ int ssum[1024];
    const int t = threadIdx.x;
    const int CH = (NN + 1023) / 1024;  // 49
    int lo = t * CH;
    int hi = min(lo + CH, NN);
    int sum = 0;
    for (int k = lo; k < hi; k++) sum += g_cnt[k];
    ssum[t] = sum;
    __syncthreads();
    for (int d = 1; d < 1024; d <<= 1) {
        int v = ssum[t];
        int add = (t >= d) ? ssum[t - d] : 0;
        __syncthreads();
        ssum[t] = v + add;
        __syncthreads();
    }
    int run = (t > 0) ? ssum[t - 1] : 0;
    for (int k = lo; k < hi; k++) {
        int c = g_cnt[k];
        g_cnt[k] = 0;                       // re-arm for next launch
        g_off[k] = run;
        g_cur[k] = run;
        g_dinv[k] = rsqrtf((float)(1 + c));
        run += c;
    }
    if (t == 1023) g_off[NN] = run;
}

__global__ void fill_kernel(const int* __restrict__ ei) {
    int e = blockIdx.x * blockDim.x + threadIdx.x;
    if (e < NE) {
        int row = ei[e];
        int col = ei[NE + e];
        int pos = atomicAdd(&g_cur[col], 1);
        g_csr_row[pos] = row;
    }
}

// ---------------------------------------------------------------------------
// tf32 tensor-core GEMM, cp.async (LDGSTS) staging, 16B per op.
// 576 threads (18 warps), 288 rows x 128 cols per block; warp = 16 rows.
// Operands arrive pre-converted/permuted/swizzled in global memory, so smem
// copies are raw bytes and all LDS accesses are bank-conflict-free.
// A-frag: a0=(g,tig) a1=(g+8,tig) a2=(g,tig+4) a3=(g+8,tig+4) (swizzled cols)
// B-frag: LDS.128 from permuted+swizzled W rows.
// ---------------------------------------------------------------------------
#define MROWS   288
#define NTHR    576
#define X_BYTES (MROWS * 512)              // 147456
#define W_BYTES 65536
#define GEMM_SMEM (X_BYTES + W_BYTES)      // 212992

__global__ __launch_bounds__(NTHR, 1)
void gemm_tc_kernel(int layer_sel) {
    extern __shared__ uint32_t sm[];
    uint32_t* sX = sm;                     // [288][128] swizzled tf32
    uint32_t* sW = sm + X_BYTES / 4;       // [128][128] permuted+swizzled

    uint32_t smem_base;
    asm("{ .reg .u64 tmp; cvta.to.shared.u64 tmp, %1; cvt.u32.u64 %0, tmp; }"
        : "=r"(smem_base) : "l"(sm));

    const int tid  = threadIdx.x;
    const int warp = tid >> 5;
    const int lane = tid & 31;
    const int g    = lane >> 2;
    const int tig  = lane & 3;
    const int row0 = blockIdx.x * MROWS;

    // Stage X tile (288x128 tf32 = 9216 uint4): 16 cp.async per thread
    const uint4* xsrc = (const uint4*)((layer_sel ? g_hidden : g_Xtf)
                                       + (size_t)row0 * 128);
#pragma unroll
    for (int it = 0; it < 16; it++) {
        int i = tid + it * NTHR;
        asm volatile("cp.async.cg.shared.global [%0], [%1], 16;"
                     :: "r"(smem_base + i * 16), "l"(xsrc + i) : "memory");
    }
    // Stage W (128x128 tf32 = 4096 uint4): ~8 cp.async per thread
    const uint4* wsrc = (const uint4*)(layer_sel ? g_Wtf23 : g_Wtf1);
    for (int i = tid; i < 4096; i += NTHR) {
        asm volatile("cp.async.cg.shared.global [%0], [%1], 16;"
                     :: "r"(smem_base + X_BYTES + i * 16), "l"(wsrc + i)
                     : "memory");
    }
    asm volatile("cp.async.commit_group;" ::: "memory");
    asm volatile("cp.async.wait_group 0;" ::: "memory");
    __syncthreads();

    float acc[16][4];
#pragma unroll
    for (int nt = 0; nt < 16; nt++)
#pragma unroll
        for (int c = 0; c < 4; c++) acc[nt][c] = 0.f;

    const int rA0 = warp * 16 + g;
    const int swzA = g << 2;               // (rA0 & 7) == g for both rows
#pragma unroll
    for (int k0 = 0; k0 < 128; k0 += 8) {
        uint32_t a0 = sX[rA0 * 128 + ((k0 + tig) ^ swzA)];
        uint32_t a1 = sX[(rA0 + 8) * 128 + ((k0 + tig) ^ swzA)];
        uint32_t a2 = sX[rA0 * 128 + ((k0 + tig + 4) ^ swzA)];
        uint32_t a3 = sX[(rA0 + 8) * 128 + ((k0 + tig + 4) ^ swzA)];
        const uint32_t* w0 = sW + (k0 + tig) * 128;
        const uint32_t* w1 = sW + (k0 + tig + 4) * 128;
        const int sw0 = tig << 2;
        const int sw1 = (tig + 4) << 2;
#pragma unroll
        for (int c = 0; c < 4; c++) {
            uint4 b0v = *(const uint4*)(w0 + ((g * 16 + c * 4) ^ sw0));
            uint4 b1v = *(const uint4*)(w1 + ((g * 16 + c * 4) ^ sw1));
#pragma unroll
            for (int j = 0; j < 4; j++) {
                uint32_t b0 = (j == 0) ? b0v.x : (j == 1) ? b0v.y
                             : (j == 2) ? b0v.z : b0v.w;
                uint32_t b1 = (j == 0) ? b1v.x : (j == 1) ? b1v.y
                             : (j == 2) ? b1v.z : b1v.w;
                int nt = c * 4 + j;
                asm volatile(
                    "mma.sync.aligned.m16n8k8.row.col.f32.tf32.tf32.f32 "
                    "{%0,%1,%2,%3}, {%4,%5,%6,%7}, {%8,%9}, {%0,%1,%2,%3};"
                    : "+f"(acc[nt][0]), "+f"(acc[nt][1]),
                      "+f"(acc[nt][2]), "+f"(acc[nt][3])
                    : "r"(a0), "r"(a1), "r"(a2), "r"(a3), "r"(b0), "r"(b1));
            }
        }
    }

    int rowA = row0 + rA0;
    int rowB = rowA + 8;
#pragma unroll
    for (int nt = 0; nt < 16; nt++) {
        int col = nt * 8 + tig * 2;
        if (rowA < NN)
            *(float2*)(g_H + rowA * 128 + col) = make_float2(acc[nt][0], acc[nt][1]);
        if (rowB < NN)
            *(float2*)(g_H + rowB * 128 + col) = make_float2(acc[nt][2], acc[nt][3]);
    }
}

// ---------------------------------------------------------------------------
// CSR aggregation, fused epilogue. One warp per target node, 4-wide gather MLP.
// layer 1: g_hidden[i] = tf32(relu(res + b1)), written SWIZZLED for gemm2.
// layer 2: out split with b2/b3 + relu.
// ---------------------------------------------------------------------------
__global__ void agg_kernel(int layer,
                           const float* __restrict__ bA,
                           const float* __restrict__ bB,
                           float* __restrict__ out) {
    int warp = (blockIdx.x * blockDim.x + threadIdx.x) >> 5;
    if (warp >= NN) return;
    const int lane = threadIdx.x & 31;
    const int i = warp;
    const int s = g_off[i];
    const int e = g_off[i + 1];
    const float di = g_dinv[i];

    float4 hv = *(const float4*)(g_H + i * 128 + lane * 4);
    float4 acc = make_float4(hv.x * di, hv.y * di, hv.z * di, hv.w * di);

    for (int base = s; base < e; base += 32) {
        int j = base + lane;
        int r = 0;
        float w = 0.f;
        if (j < e) { r = g_csr_row[j]; w = g_dinv[r]; }
        int cnt = min(32, e - base);
        int k = 0;
        for (; k + 4 <= cnt; k += 4) {
            int rr[4]; float ww[4];
#pragma unroll
            for (int u = 0; u < 4; u++) {
                rr[u] = __shfl_sync(0xffffffffu, r, k + u);
                ww[u] = __shfl_sync(0xffffffffu, w, k + u);
            }
            float4 v[4];
#pragma unroll
            for (int u = 0; u < 4; u++)
                v[u] = *(const float4*)(g_H + rr[u] * 128 + lane * 4);
#pragma unroll
            for (int u = 0; u < 4; u++) {
                acc.x += ww[u] * v[u].x;
                acc.y += ww[u] * v[u].y;
                acc.z += ww[u] * v[u].z;
                acc.w += ww[u] * v[u].w;
            }
        }
        for (; k < cnt; k++) {
            int   rr = __shfl_sync(0xffffffffu, r, k);
            float ww = __shfl_sync(0xffffffffu, w, k);
            float4 v = *(const float4*)(g_H + rr * 128 + lane * 4);
            acc.x += ww * v.x;
            acc.y += ww * v.y;
            acc.z += ww * v.z;
            acc.w += ww * v.w;
        }
    }
    acc.x *= di; acc.y *= di; acc.z *= di; acc.w *= di;

    const int c4 = lane * 4;
    if (layer == 1) {
        float4 b = *(const float4*)(bA + c4);
        uint4 h;
        h.x = f2tf32(fmaxf(acc.x + b.x, 0.f));
        h.y = f2tf32(fmaxf(acc.y + b.y, 0.f));
        h.z = f2tf32(fmaxf(acc.z + b.z, 0.f));
        h.w = f2tf32(fmaxf(acc.w + b.w, 0.f));
        int pc4 = c4 ^ ((i & 7) << 2);     // swizzled layout for gemm2
        *(uint4*)(g_hidden + i * 128 + pc4) = h;
    } else {
        float4 b;
        float* dst;
        if (c4 < 64) {
            b = *(const float4*)(bA + c4);
            dst = out + i * 64 + c4;
        } else {
            b = *(const float4*)(bB + (c4 - 64));
            dst = out + NN * 64 + i * 64 + (c4 - 64);
        }
        float4 rr;
        rr.x = fmaxf(acc.x + b.x, 0.f);
        rr.y = fmaxf(acc.y + b.y, 0.f);
        rr.z = fmaxf(acc.z + b.z, 0.f);
        rr.w = fmaxf(acc.w + b.w, 0.f);
        *(float4*)dst = rr;
    }
}

// ---------------------------------------------------------------------------
extern "C" void kernel_launch(void* const* d_in, const int* in_sizes, int n_in,
                              void* d_out, int out_size) {
    const float* x  = (const float*)d_in[0];
    const int*   ei = (const int*)d_in[1];   // int32 (JAX default, no x64)
    const float* W1 = (const float*)d_in[2];
    const float* b1 = (const float*)d_in[3];
    const float* W2 = (const float*)d_in[4];
    const float* b2 = (const float*)d_in[5];
    const float* W3 = (const float*)d_in[6];
    const float* b3 = (const float*)d_in[7];
    float* out = (float*)d_out;

    cudaFuncSetAttribute(gemm_tc_kernel,
                         cudaFuncAttributeMaxDynamicSharedMemorySize, GEMM_SMEM);

    const int gemm_blocks = NNP / MROWS;     // 174
    const int agg_blocks  = (NN + 7) / 8;    // 8 warps/block

    prep_kernel<<<PREP_BLOCKS, 256>>>(x, W1, W2, W3, ei);           // 0
    scan_kernel<<<1, 1024>>>();                                     // 1
    fill_kernel<<<(NE + 255) / 256, 256>>>(ei);                     // 2
    gemm_tc_kernel<<<gemm_blocks, NTHR, GEMM_SMEM>>>(0);            // 3 <- profiled
    agg_kernel<<<agg_blocks, 256>>>(1, b1, nullptr, nullptr);       // 4
    gemm_tc_kernel<<<gemm_blocks, NTHR, GEMM_SMEM>>>(1);            // 5
    agg_kernel<<<agg_blocks, 256>>>(2, b2, b3, out);                // 6
}

// round 14
// speedup vs baseline: 1.1715x; 1.1715x over previous
#include <cuda_runtime.h>
#include <cuda_bf16.h>
#include <cstdint>

#define NN  50000
#define NE  800000
#define NNP 50112              // 174 * 288, padded row count
#define SCAN_BLOCKS 196        // ceil(NN/256)

__device__ int      g_cnt[NN];          // zero at launch; re-zeroed by scanC
__device__ int      g_off[NN + 1];
__device__ int      g_cur[NN];
__device__ int      g_csr_row[NE];
__device__ int      g_bsum[SCAN_BLOCKS];
__device__ int      g_boff[SCAN_BLOCKS];
__device__ float    g_dinv[NN];
__device__ float    g_H[NN * 128];         // fp32 linear output of current layer
__device__ uint32_t g_hidden[NNP * 128];   // relu(layer1) as tf32, swizzled
__device__ uint32_t g_Xtf[NNP * 128];      // x as tf32, swizzled
__device__ uint32_t g_Wtf1[128 * 128];     // W1 tf32, permuted+swizzled
__device__ uint32_t g_Wtf23[128 * 128];    // [W2|W3] tf32, permuted+swizzled

__device__ __forceinline__ uint32_t f2tf32(float f) {
    uint32_t r;
    asm("cvt.rna.tf32.f32 %0, %1;" : "=r"(r) : "f"(f));
    return r;
}

// ---------------------------------------------------------------------------
// hist: in-degree histogram (g_cnt starts zero; scanC re-zeroes it)
// ---------------------------------------------------------------------------
__global__ void hist_kernel(const int* __restrict__ ei) {
    int e = blockIdx.x * blockDim.x + threadIdx.x;
    if (e < NE) atomicAdd(&g_cnt[ei[NE + e]], 1);
}

// ---------------------------------------------------------------------------
// cvtX: x -> tf32, column-swizzled (physical c4 = c4 ^ ((row&7)<<2))
// ---------------------------------------------------------------------------
__global__ void cvtX_kernel(const float* __restrict__ x) {
    int i = blockIdx.x * blockDim.x + threadIdx.x;   // uint4 over NN*32
    if (i < NN * 32) {
        int row = i >> 5;
        int c4  = (i & 31) << 2;
        float4 v = ((const float4*)x)[i];
        uint4 u;
        u.x = f2tf32(v.x); u.y = f2tf32(v.y);
        u.z = f2tf32(v.z); u.w = f2tf32(v.w);
        int pc4 = c4 ^ ((row & 7) << 2);
        ((uint4*)g_Xtf)[row * 32 + (pc4 >> 2)] = u;
    }
}

// ---------------------------------------------------------------------------
// packW: W1 / [W2|W3] -> tf32, permuted+swizzled:
//   physical col = ((n&7)*16 + (n>>3)) ^ ((k&7)<<2)
// ---------------------------------------------------------------------------
__global__ void packW_kernel(const float* __restrict__ W1,
                             const float* __restrict__ W2,
                             const float* __restrict__ W3) {
    int j = blockIdx.x * blockDim.x + threadIdx.x;   // float4 over 2*4096
    if (j >= 8192) return;
    int k, c4;
    float4 v;
    uint32_t* dst;
    if (j < 4096) {
        k = j >> 5; c4 = (j & 31) << 2;
        v = ((const float4*)W1)[j];
        dst = g_Wtf1;
    } else {
        int jj = j - 4096;
        k = jj >> 5; c4 = (jj & 31) << 2;
        if (c4 < 64) v = *(const float4*)(W2 + k * 64 + c4);
        else         v = *(const float4*)(W3 + k * 64 + (c4 - 64));
        dst = g_Wtf23;
    }
    float vv[4] = {v.x, v.y, v.z, v.w};
    int swz = (k & 7) << 2;
#pragma unroll
    for (int u = 0; u < 4; u++) {
        int n = c4 + u;
        int pcol = ((n & 7) * 16 + (n >> 3)) ^ swz;
        dst[k * 128 + pcol] = f2tf32(vv[u]);
    }
}

// ---------------------------------------------------------------------------
// Multi-block exclusive scan of g_cnt:
//  sumA:  per-block (256 elems) sums -> g_bsum
//  scanB: 1 block scans g_bsum -> g_boff (exclusive); writes g_off[NN]
//  scanC: per-block local scan + g_off/g_cur/g_dinv; re-zeroes g_cnt
// ---------------------------------------------------------------------------
__global__ void sumA_kernel() {
    __shared__ int sd[256];
    int t = threadIdx.x;
    int i = blockIdx.x * 256 + t;
    sd[t] = (i < NN) ? g_cnt[i] : 0;
    __syncthreads();
    for (int d = 128; d > 0; d >>= 1) {
        if (t < d) sd[t] += sd[t + d];
        __syncthreads();
    }
    if (t == 0) g_bsum[blockIdx.x] = sd[0];
}

__global__ void scanB_kernel() {
    __shared__ int sd[256];
    int t = threadIdx.x;
    sd[t] = (t < SCAN_BLOCKS) ? g_bsum[t] : 0;
    __syncthreads();
    for (int d = 1; d < 256; d <<= 1) {
        int v = sd[t];
        int add = (t >= d) ? sd[t - d] : 0;
        __syncthreads();
        sd[t] = v + add;
        __syncthreads();
    }
    if (t < SCAN_BLOCKS) g_boff[t] = (t > 0) ? sd[t - 1] : 0;
    if (t == 255) g_off[NN] = sd[SCAN_BLOCKS - 1];
}

__global__ void scanC_kernel() {
    __shared__ int sd[256];
    int t = threadIdx.x;
    int i = blockIdx.x * 256 + t;
    int c = (i < NN) ? g_cnt[i] : 0;
    sd[t] = c;
    __syncthreads();
    for (int d = 1; d < 256; d <<= 1) {
        int v = sd[t];
        int add = (t >= d) ? sd[t - d] : 0;
        __syncthreads();
        sd[t] = v + add;
        __syncthreads();
    }
    if (i < NN) {
        int off = g_boff[blockIdx.x] + sd[t] - c;   // exclusive
        g_off[i] = off;
        g_cur[i] = off;
        g_dinv[i] = rsqrtf((float)(1 + c));
        g_cnt[i] = 0;                               // re-arm for next launch
    }
}

__global__ void fill_kernel(const int* __restrict__ ei) {
    int e = blockIdx.x * blockDim.x + threadIdx.x;
    if (e < NE) {
        int row = ei[e];
        int col = ei[NE + e];
        int pos = atomicAdd(&g_cur[col], 1);
        g_csr_row[pos] = row;
    }
}

// ---------------------------------------------------------------------------
// tf32 tensor-core GEMM, cp.async (LDGSTS) staging, 16B per op.
// 576 threads (18 warps), 288 rows x 128 cols per block; warp = 16 rows.
// Operands pre-converted/permuted/swizzled in global memory -> raw byte
// copies into smem, all LDS conflict-free.
// ---------------------------------------------------------------------------
#define MROWS   288
#define NTHR    576
#define X_BYTES (MROWS * 512)              // 147456
#define W_BYTES 65536
#define GEMM_SMEM (X_BYTES + W_BYTES)      // 212992

__global__ __launch_bounds__(NTHR, 1)
void gemm_tc_kernel(int layer_sel) {
    extern __shared__ uint32_t sm[];
    uint32_t* sX = sm;                     // [288][128] swizzled tf32
    uint32_t* sW = sm + X_BYTES / 4;       // [128][128] permuted+swizzled

    uint32_t smem_base;
    asm("{ .reg .u64 tmp; cvta.to.shared.u64 tmp, %1; cvt.u32.u64 %0, tmp; }"
        : "=r"(smem_base) : "l"(sm));

    const int tid  = threadIdx.x;
    const int warp = tid >> 5;
    const int lane = tid & 31;
    const int g    = lane >> 2;
    const int tig  = lane & 3;
    const int row0 = blockIdx.x * MROWS;

    const uint4* xsrc = (const uint4*)((layer_sel ? g_hidden : g_Xtf)
                                       + (size_t)row0 * 128);
#pragma unroll
    for (int it = 0; it < 16; it++) {
        int i = tid + it * NTHR;
        asm volatile("cp.async.cg.shared.global [%0], [%1], 16;"
                     :: "r"(smem_base + i * 16), "l"(xsrc + i) : "memory");
    }
    const uint4* wsrc = (const uint4*)(layer_sel ? g_Wtf23 : g_Wtf1);
    for (int i = tid; i < 4096; i += NTHR) {
        asm volatile("cp.async.cg.shared.global [%0], [%1], 16;"
                     :: "r"(smem_base + X_BYTES + i * 16), "l"(wsrc + i)
                     : "memory");
    }
    asm volatile("cp.async.commit_group;" ::: "memory");
    asm volatile("cp.async.wait_group 0;" ::: "memory");
    __syncthreads();

    float acc[16][4];
#pragma unroll
    for (int nt = 0; nt < 16; nt++)
#pragma unroll
        for (int c = 0; c < 4; c++) acc[nt][c] = 0.f;

    const int rA0 = warp * 16 + g;
    const int swzA = g << 2;
#pragma unroll
    for (int k0 = 0; k0 < 128; k0 += 8) {
        uint32_t a0 = sX[rA0 * 128 + ((k0 + tig) ^ swzA)];
        uint32_t a1 = sX[(rA0 + 8) * 128 + ((k0 + tig) ^ swzA)];
        uint32_t a2 = sX[rA0 * 128 + ((k0 + tig + 4) ^ swzA)];
        uint32_t a3 = sX[(rA0 + 8) * 128 + ((k0 + tig + 4) ^ swzA)];
        const uint32_t* w0 = sW + (k0 + tig) * 128;
        const uint32_t* w1 = sW + (k0 + tig + 4) * 128;
        const int sw0 = tig << 2;
        const int sw1 = (tig + 4) << 2;
#pragma unroll
        for (int c = 0; c < 4; c++) {
            uint4 b0v = *(const uint4*)(w0 + ((g * 16 + c * 4) ^ sw0));
            uint4 b1v = *(const uint4*)(w1 + ((g * 16 + c * 4) ^ sw1));
#pragma unroll
            for (int j = 0; j < 4; j++) {
                uint32_t b0 = (j == 0) ? b0v.x : (j == 1) ? b0v.y
                             : (j == 2) ? b0v.z : b0v.w;
                uint32_t b1 = (j == 0) ? b1v.x : (j == 1) ? b1v.y
                             : (j == 2) ? b1v.z : b1v.w;
                int nt = c * 4 + j;
                asm volatile(
                    "mma.sync.aligned.m16n8k8.row.col.f32.tf32.tf32.f32 "
                    "{%0,%1,%2,%3}, {%4,%5,%6,%7}, {%8,%9}, {%0,%1,%2,%3};"
                    : "+f"(acc[nt][0]), "+f"(acc[nt][1]),
                      "+f"(acc[nt][2]), "+f"(acc[nt][3])
                    : "r"(a0), "r"(a1), "r"(a2), "r"(a3), "r"(b0), "r"(b1));
            }
        }
    }

    int rowA = row0 + rA0;
    int rowB = rowA + 8;
#pragma unroll
    for (int nt = 0; nt < 16; nt++) {
        int col = nt * 8 + tig * 2;
        if (rowA < NN)
            *(float2*)(g_H + rowA * 128 + col) = make_float2(acc[nt][0], acc[nt][1]);
        if (rowB < NN)
            *(float2*)(g_H + rowB * 128 + col) = make_float2(acc[nt][2], acc[nt][3]);
    }
}

// ---------------------------------------------------------------------------
// CSR aggregation, fused epilogue. One warp per target node, 8-wide gather MLP.
// layer 1: g_hidden[i] = tf32(relu(res + b1)), written SWIZZLED for gemm2.
// layer 2: out split with b2/b3 + relu.
// ---------------------------------------------------------------------------
__global__ void agg_kernel(int layer,
                           const float* __restrict__ bA,
                           const float* __restrict__ bB,
                           float* __restrict__ out) {
    int warp = (blockIdx.x * blockDim.x + threadIdx.x) >> 5;
    if (warp >= NN) return;
    const int lane = threadIdx.x & 31;
    const int i = warp;
    const int s = g_off[i];
    const int e = g_off[i + 1];
    const float di = g_dinv[i];

    float4 hv = *(const float4*)(g_H + i * 128 + lane * 4);
    float4 acc = make_float4(hv.x * di, hv.y * di, hv.z * di, hv.w * di);

    for (int base = s; base < e; base += 32) {
        int j = base + lane;
        int r = 0;
        float w = 0.f;
        if (j < e) { r = g_csr_row[j]; w = g_dinv[r]; }
        int cnt = min(32, e - base);
        int k = 0;
        // 8-wide batches: 8 independent LDG.128 in flight per step
        for (; k + 8 <= cnt; k += 8) {
            int rr[8]; float ww[8];
#pragma unroll
            for (int u = 0; u < 8; u++) {
                rr[u] = __shfl_sync(0xffffffffu, r, k + u);
                ww[u] = __shfl_sync(0xffffffffu, w, k + u);
            }
            float4 v[8];
#pragma unroll
            for (int u = 0; u < 8; u++)
                v[u] = *(const float4*)(g_H + rr[u] * 128 + lane * 4);
#pragma unroll
            for (int u = 0; u < 8; u++) {
                acc.x += ww[u] * v[u].x;
                acc.y += ww[u] * v[u].y;
                acc.z += ww[u] * v[u].z;
                acc.w += ww[u] * v[u].w;
            }
        }
        for (; k < cnt; k++) {
            int   rr = __shfl_sync(0xffffffffu, r, k);
            float ww = __shfl_sync(0xffffffffu, w, k);
            float4 v = *(const float4*)(g_H + rr * 128 + lane * 4);
            acc.x += ww * v.x;
            acc.y += ww * v.y;
            acc.z += ww * v.z;
            acc.w += ww * v.w;
        }
    }
    acc.x *= di; acc.y *= di; acc.z *= di; acc.w *= di;

    const int c4 = lane * 4;
    if (layer == 1) {
        float4 b = *(const float4*)(bA + c4);
        uint4 h;
        h.x = f2tf32(fmaxf(acc.x + b.x, 0.f));
        h.y = f2tf32(fmaxf(acc.y + b.y, 0.f));
        h.z = f2tf32(fmaxf(acc.z + b.z, 0.f));
        h.w = f2tf32(fmaxf(acc.w + b.w, 0.f));
        int pc4 = c4 ^ ((i & 7) << 2);     // swizzled layout for gemm2
        *(uint4*)(g_hidden + i * 128 + pc4) = h;
    } else {
        float4 b;
        float* dst;
        if (c4 < 64) {
            b = *(const float4*)(bA + c4);
            dst = out + i * 64 + c4;
        } else {
            b = *(const float4*)(bB + (c4 - 64));
            dst = out + NN * 64 + i * 64 + (c4 - 64);
        }
        float4 rr;
        rr.x = fmaxf(acc.x + b.x, 0.f);
        rr.y = fmaxf(acc.y + b.y, 0.f);
        rr.z = fmaxf(acc.z + b.z, 0.f);
        rr.w = fmaxf(acc.w + b.w, 0.f);
        *(float4*)dst = rr;
    }
}

// ---------------------------------------------------------------------------
extern "C" void kernel_launch(void* const* d_in, const int* in_sizes, int n_in,
                              void* d_out, int out_size) {
    const float* x  = (const float*)d_in[0];
    const int*   ei = (const int*)d_in[1];   // int32 (JAX default, no x64)
    const float* W1 = (const float*)d_in[2];
    const float* b1 = (const float*)d_in[3];
    const float* W2 = (const float*)d_in[4];
    const float* b2 = (const float*)d_in[5];
    const float* W3 = (const float*)d_in[6];
    const float* b3 = (const float*)d_in[7];
    float* out = (float*)d_out;

    cudaFuncSetAttribute(gemm_tc_kernel,
                         cudaFuncAttributeMaxDynamicSharedMemorySize, GEMM_SMEM);

    const int gemm_blocks = NNP / MROWS;     // 174
    const int agg_blocks  = (NN + 7) / 8;    // 8 warps/block

    hist_kernel<<<(NE + 255) / 256, 256>>>(ei);                     // 0
    cvtX_kernel<<<(NN * 32 + 255) / 256, 256>>>(x);                 // 1
    packW_kernel<<<32, 256>>>(W1, W2, W3);                          // 2
    gemm_tc_kernel<<<gemm_blocks, NTHR, GEMM_SMEM>>>(0);            // 3 <- profiled
    sumA_kernel<<<SCAN_BLOCKS, 256>>>();                            // 4
    scanB_kernel<<<1, 256>>>();                                     // 5
    scanC_kernel<<<SCAN_BLOCKS, 256>>>();                           // 6
    fill_kernel<<<(NE + 255) / 256, 256>>>(ei);                     // 7
    agg_kernel<<<agg_blocks, 256>>>(1, b1, nullptr, nullptr);       // 8
    gemm_tc_kernel<<<gemm_blocks, NTHR, GEMM_SMEM>>>(1);            // 9
    agg_kernel<<<agg_blocks, 256>>>(2, b2, b3, out);                // 10
}

// round 16
// speedup vs baseline: 1.6393x; 1.3993x over previous
#include <cuda_runtime.h>
#include <cuda_bf16.h>
#include <cstdint>

#define NN  50000
#define NE  800000
#define NNP 50112              // 174 * 288, padded row count
#define SCAN_BLOCKS 196        // ceil(NN/256)

__device__ int      g_cnt[NN];          // zero at launch; re-zeroed by scanC
__device__ int      g_off[NN + 1];
__device__ int      g_cur[NN];
__device__ int      g_csr_row[NE];
__device__ int      g_bsum[SCAN_BLOCKS];
__device__ int      g_boff[SCAN_BLOCKS];
__device__ float    g_dinv[NN];
__device__ float    g_H[NN * 128];         // fp32 linear output of current layer
__device__ uint32_t g_hidden[NNP * 128];   // relu(layer1) as tf32, swizzled
__device__ uint32_t g_Xtf[NNP * 128];      // x as tf32, swizzled
__device__ uint32_t g_Wtf1[128 * 128];     // W1 tf32, permuted+swizzled
__device__ uint32_t g_Wtf23[128 * 128];    // [W2|W3] tf32, permuted+swizzled

__device__ __forceinline__ uint32_t f2tf32(float f) {
    uint32_t r;
    asm("cvt.rna.tf32.f32 %0, %1;" : "=r"(r) : "f"(f));
    return r;
}

// ---------------------------------------------------------------------------
// hist: in-degree histogram (g_cnt starts zero; scanC re-zeroes it)
// ---------------------------------------------------------------------------
__global__ void hist_kernel(const int* __restrict__ ei) {
    int e = blockIdx.x * blockDim.x + threadIdx.x;
    if (e < NE) atomicAdd(&g_cnt[ei[NE + e]], 1);
}

// ---------------------------------------------------------------------------
// cvtX: x -> tf32, column-swizzled (physical c4 = c4 ^ ((row&7)<<2))
// ---------------------------------------------------------------------------
__global__ void cvtX_kernel(const float* __restrict__ x) {
    int i = blockIdx.x * blockDim.x + threadIdx.x;   // uint4 over NN*32
    if (i < NN * 32) {
        int row = i >> 5;
        int c4  = (i & 31) << 2;
        float4 v = ((const float4*)x)[i];
        uint4 u;
        u.x = f2tf32(v.x); u.y = f2tf32(v.y);
        u.z = f2tf32(v.z); u.w = f2tf32(v.w);
        int pc4 = c4 ^ ((row & 7) << 2);
        ((uint4*)g_Xtf)[row * 32 + (pc4 >> 2)] = u;
    }
}

// ---------------------------------------------------------------------------
// packW: W1 / [W2|W3] -> tf32, permuted+swizzled:
//   physical col = ((n&7)*16 + (n>>3)) ^ ((k&7)<<2)
// ---------------------------------------------------------------------------
__global__ void packW_kernel(const float* __restrict__ W1,
                             const float* __restrict__ W2,
                             const float* __restrict__ W3) {
    int j = blockIdx.x * blockDim.x + threadIdx.x;   // float4 over 2*4096
    if (j >= 8192) return;
    int k, c4;
    float4 v;
    uint32_t* dst;
    if (j < 4096) {
        k = j >> 5; c4 = (j & 31) << 2;
        v = ((const float4*)W1)[j];
        dst = g_Wtf1;
    } else {
        int jj = j - 4096;
        k = jj >> 5; c4 = (jj & 31) << 2;
        if (c4 < 64) v = *(const float4*)(W2 + k * 64 + c4);
        else         v = *(const float4*)(W3 + k * 64 + (c4 - 64));
        dst = g_Wtf23;
    }
    float vv[4] = {v.x, v.y, v.z, v.w};
    int swz = (k & 7) << 2;
#pragma unroll
    for (int u = 0; u < 4; u++) {
        int n = c4 + u;
        int pcol = ((n & 7) * 16 + (n >> 3)) ^ swz;
        dst[k * 128 + pcol] = f2tf32(vv[u]);
    }
}

// ---------------------------------------------------------------------------
// Multi-block exclusive scan of g_cnt (sumA -> scanB -> scanC)
// ---------------------------------------------------------------------------
__global__ void sumA_kernel() {
    __shared__ int sd[256];
    int t = threadIdx.x;
    int i = blockIdx.x * 256 + t;
    sd[t] = (i < NN) ? g_cnt[i] : 0;
    __syncthreads();
    for (int d = 128; d > 0; d >>= 1) {
        if (t < d) sd[t] += sd[t + d];
        __syncthreads();
    }
    if (t == 0) g_bsum[blockIdx.x] = sd[0];
}

__global__ void scanB_kernel() {
    __shared__ int sd[256];
    int t = threadIdx.x;
    sd[t] = (t < SCAN_BLOCKS) ? g_bsum[t] : 0;
    __syncthreads();
    for (int d = 1; d < 256; d <<= 1) {
        int v = sd[t];
        int add = (t >= d) ? sd[t - d] : 0;
        __syncthreads();
        sd[t] = v + add;
        __syncthreads();
    }
    if (t < SCAN_BLOCKS) g_boff[t] = (t > 0) ? sd[t - 1] : 0;
    if (t == 255) g_off[NN] = sd[SCAN_BLOCKS - 1];
}

__global__ void scanC_kernel() {
    __shared__ int sd[256];
    int t = threadIdx.x;
    int i = blockIdx.x * 256 + t;
    int c = (i < NN) ? g_cnt[i] : 0;
    sd[t] = c;
    __syncthreads();
    for (int d = 1; d < 256; d <<= 1) {
        int v = sd[t];
        int add = (t >= d) ? sd[t - d] : 0;
        __syncthreads();
        sd[t] = v + add;
        __syncthreads();
    }
    if (i < NN) {
        int off = g_boff[blockIdx.x] + sd[t] - c;   // exclusive
        g_off[i] = off;
        g_cur[i] = off;
        g_dinv[i] = rsqrtf((float)(1 + c));
        g_cnt[i] = 0;                               // re-arm for next launch
    }
}

__global__ void fill_kernel(const int* __restrict__ ei) {
    int e = blockIdx.x * blockDim.x + threadIdx.x;
    if (e < NE) {
        int row = ei[e];
        int col = ei[NE + e];
        int pos = atomicAdd(&g_cur[col], 1);
        g_csr_row[pos] = row;
    }
}

// ---------------------------------------------------------------------------
// tf32 tensor-core GEMM, cp.async.bulk (TMA) staging.
// 576 threads (18 warps), 288 rows x 128 cols per block; warp = 16 rows.
// Operands pre-converted/permuted/swizzled in global memory -> raw byte bulk
// copies into smem (4 TMA ops replace 13312 LDGSTS), all LDS conflict-free.
// ---------------------------------------------------------------------------
#define MROWS   288
#define NTHR    576
#define X_BYTES (MROWS * 512)              // 147456
#define W_BYTES 65536
#define MBAR_OFF (X_BYTES + W_BYTES)       // 212992 (8-aligned)
#define GEMM_SMEM (MBAR_OFF + 16)

__global__ __launch_bounds__(NTHR, 1)
void gemm_tc_kernel(int layer_sel) {
    extern __shared__ uint32_t sm[];
    uint32_t* sX = sm;                     // [288][128] swizzled tf32
    uint32_t* sW = sm + X_BYTES / 4;       // [128][128] permuted+swizzled

    uint32_t smem_base;
    asm("{ .reg .u64 tmp; cvta.to.shared.u64 tmp, %1; cvt.u32.u64 %0, tmp; }"
        : "=r"(smem_base) : "l"(sm));
    const uint32_t mbar = smem_base + MBAR_OFF;

    const int tid  = threadIdx.x;
    const int warp = tid >> 5;
    const int lane = tid & 31;
    const int g    = lane >> 2;
    const int tig  = lane & 3;
    const int row0 = blockIdx.x * MROWS;

    if (tid == 0) {
        asm volatile("mbarrier.init.shared.b64 [%0], %1;"
                     :: "r"(mbar), "r"(1u) : "memory");
    }
    __syncthreads();
    if (tid == 0) {
        asm volatile("mbarrier.arrive.expect_tx.shared.b64 _, [%0], %1;"
                     :: "r"(mbar), "r"((uint32_t)(X_BYTES + W_BYTES))
                     : "memory");
        const char* wsrc = (const char*)(layer_sel ? g_Wtf23 : g_Wtf1);
        asm volatile(
            "cp.async.bulk.shared::cta.global.mbarrier::complete_tx::bytes "
            "[%0], [%1], %2, [%3];"
            :: "r"(smem_base + X_BYTES), "l"(wsrc), "r"((uint32_t)W_BYTES),
               "r"(mbar) : "memory");
        const char* xsrc = (const char*)(layer_sel ? g_hidden : g_Xtf)
                           + (size_t)row0 * 512;
#pragma unroll
        for (int tch = 0; tch < 3; tch++) {
            asm volatile(
                "cp.async.bulk.shared::cta.global.mbarrier::complete_tx::bytes "
                "[%0], [%1], %2, [%3];"
                :: "r"(smem_base + tch * 49152),
                   "l"(xsrc + (size_t)tch * 49152), "r"(49152u),
                   "r"(mbar) : "memory");
        }
    }
    // Wait for all 212992 bytes (parity 0) — production try_wait pattern.
    {
        uint32_t done;
        asm volatile(
            "{\n\t.reg .pred p;\n\t"
            "mbarrier.try_wait.parity.acquire.cta.shared::cta.b64 p, [%1], %2;\n\t"
            "selp.b32 %0, 1, 0, p;\n\t}"
            : "=r"(done) : "r"(mbar), "r"(0u) : "memory");
        if (!done) {
            asm volatile(
                "{\n\t.reg .pred P1;\n\t"
                "WAIT_LOOP_%=:\n\t"
                "mbarrier.try_wait.parity.acquire.cta.shared::cta.b64 P1, [%0], %1, 0x989680;\n\t"
                "@P1 bra.uni WAIT_DONE_%=;\n\t"
                "bra.uni WAIT_LOOP_%=;\n\t"
                "WAIT_DONE_%=:\n\t}"
                :: "r"(mbar), "r"(0u) : "memory");
        }
    }

    float acc[16][4];
#pragma unroll
    for (int nt = 0; nt < 16; nt++)
#pragma unroll
        for (int c = 0; c < 4; c++) acc[nt][c] = 0.f;

    const int rA0 = warp * 16 + g;
    const int swzA = g << 2;
#pragma unroll
    for (int k0 = 0; k0 < 128; k0 += 8) {
        uint32_t a0 = sX[rA0 * 128 + ((k0 + tig) ^ swzA)];
        uint32_t a1 = sX[(rA0 + 8) * 128 + ((k0 + tig) ^ swzA)];
        uint32_t a2 = sX[rA0 * 128 + ((k0 + tig + 4) ^ swzA)];
        uint32_t a3 = sX[(rA0 + 8) * 128 + ((k0 + tig + 4) ^ swzA)];
        const uint32_t* w0 = sW + (k0 + tig) * 128;
        const uint32_t* w1 = sW + (k0 + tig + 4) * 128;
        const int sw0 = tig << 2;
        const int sw1 = (tig + 4) << 2;
#pragma unroll
        for (int c = 0; c < 4; c++) {
            uint4 b0v = *(const uint4*)(w0 + ((g * 16 + c * 4) ^ sw0));
            uint4 b1v = *(const uint4*)(w1 + ((g * 16 + c * 4) ^ sw1));
#pragma unroll
            for (int j = 0; j < 4; j++) {
                uint32_t b0 = (j == 0) ? b0v.x : (j == 1) ? b0v.y
                             : (j == 2) ? b0v.z : b0v.w;
                uint32_t b1 = (j == 0) ? b1v.x : (j == 1) ? b1v.y
                             : (j == 2) ? b1v.z : b1v.w;
                int nt = c * 4 + j;
                asm volatile(
                    "mma.sync.aligned.m16n8k8.row.col.f32.tf32.tf32.f32 "
                    "{%0,%1,%2,%3}, {%4,%5,%6,%7}, {%8,%9}, {%0,%1,%2,%3};"
                    : "+f"(acc[nt][0]), "+f"(acc[nt][1]),
                      "+f"(acc[nt][2]), "+f"(acc[nt][3])
                    : "r"(a0), "r"(a1), "r"(a2), "r"(a3), "r"(b0), "r"(b1));
            }
        }
    }

    int rowA = row0 + rA0;
    int rowB = rowA + 8;
#pragma unroll
    for (int nt = 0; nt < 16; nt++) {
        int col = nt * 8 + tig * 2;
        if (rowA < NN)
            *(float2*)(g_H + rowA * 128 + col) = make_float2(acc[nt][0], acc[nt][1]);
        if (rowB < NN)
            *(float2*)(g_H + rowB * 128 + col) = make_float2(acc[nt][2], acc[nt][3]);
    }
}

// ---------------------------------------------------------------------------
// CSR aggregation, fused epilogue. One warp per target node, 8-wide gather MLP.
// layer 1: g_hidden[i] = tf32(relu(res + b1)), written SWIZZLED for gemm2.
// layer 2: out split with b2/b3 + relu.
// ---------------------------------------------------------------------------
__global__ void agg_kernel(int layer,
                           const float* __restrict__ bA,
                           const float* __restrict__ bB,
                           float* __restrict__ out) {
    int warp = (blockIdx.x * blockDim.x + threadIdx.x) >> 5;
    if (warp >= NN) return;
    const int lane = threadIdx.x & 31;
    const int i = warp;
    const int s = g_off[i];
    const int e = g_off[i + 1];
    const float di = g_dinv[i];

    float4 hv = *(const float4*)(g_H + i * 128 + lane * 4);
    float4 acc = make_float4(hv.x * di, hv.y * di, hv.z * di, hv.w * di);

    for (int base = s; base < e; base += 32) {
        int j = base + lane;
        int r = 0;
        float w = 0.f;
        if (j < e) { r = g_csr_row[j]; w = g_dinv[r]; }
        int cnt = min(32, e - base);
        int k = 0;
        for (; k + 8 <= cnt; k += 8) {
            int rr[8]; float ww[8];
#pragma unroll
            for (int u = 0; u < 8; u++) {
                rr[u] = __shfl_sync(0xffffffffu, r, k + u);
                ww[u] = __shfl_sync(0xffffffffu, w, k + u);
            }
            float4 v[8];
#pragma unroll
            for (int u = 0; u < 8; u++)
                v[u] = *(const float4*)(g_H + rr[u] * 128 + lane * 4);
#pragma unroll
            for (int u = 0; u < 8; u++) {
                acc.x += ww[u] * v[u].x;
                acc.y += ww[u] * v[u].y;
                acc.z += ww[u] * v[u].z;
                acc.w += ww[u] * v[u].w;
            }
        }
        for (; k < cnt; k++) {
            int   rr = __shfl_sync(0xffffffffu, r, k);
            float ww = __shfl_sync(0xffffffffu, w, k);
            float4 v = *(const float4*)(g_H + rr * 128 + lane * 4);
            acc.x += ww * v.x;
            acc.y += ww * v.y;
            acc.z += ww * v.z;
            acc.w += ww * v.w;
        }
    }
    acc.x *= di; acc.y *= di; acc.z *= di; acc.w *= di;

    const int c4 = lane * 4;
    if (layer == 1) {
        float4 b = *(const float4*)(bA + c4);
        uint4 h;
        h.x = f2tf32(fmaxf(acc.x + b.x, 0.f));
        h.y = f2tf32(fmaxf(acc.y + b.y, 0.f));
        h.z = f2tf32(fmaxf(acc.z + b.z, 0.f));
        h.w = f2tf32(fmaxf(acc.w + b.w, 0.f));
        int pc4 = c4 ^ ((i & 7) << 2);     // swizzled layout for gemm2
        *(uint4*)(g_hidden + i * 128 + pc4) = h;
    } else {
        float4 b;
        float* dst;
        if (c4 < 64) {
            b = *(const float4*)(bA + c4);
            dst = out + i * 64 + c4;
        } else {
            b = *(const float4*)(bB + (c4 - 64));
            dst = out + NN * 64 + i * 64 + (c4 - 64);
        }
        float4 rr;
        rr.x = fmaxf(acc.x + b.x, 0.f);
        rr.y = fmaxf(acc.y + b.y, 0.f);
        rr.z = fmaxf(acc.z + b.z, 0.f);
        rr.w = fmaxf(acc.w + b.w, 0.f);
        *(float4*)dst = rr;
    }
}

// ---------------------------------------------------------------------------
extern "C" void kernel_launch(void* const* d_in, const int* in_sizes, int n_in,
                              void* d_out, int out_size) {
    const float* x  = (const float*)d_in[0];
    const int*   ei = (const int*)d_in[1];   // int32 (JAX default, no x64)
    const float* W1 = (const float*)d_in[2];
    const float* b1 = (const float*)d_in[3];
    const float* W2 = (const float*)d_in[4];
    const float* b2 = (const float*)d_in[5];
    const float* W3 = (const float*)d_in[6];
    const float* b3 = (const float*)d_in[7];
    float* out = (float*)d_out;

    cudaFuncSetAttribute(gemm_tc_kernel,
                         cudaFuncAttributeMaxDynamicSharedMemorySize, GEMM_SMEM);

    const int gemm_blocks = NNP / MROWS;     // 174
    const int agg_blocks  = (NN + 7) / 8;    // 8 warps/block

    hist_kernel<<<(NE + 255) / 256, 256>>>(ei);                     // 0
    cvtX_kernel<<<(NN * 32 + 255) / 256, 256>>>(x);                 // 1
    packW_kernel<<<32, 256>>>(W1, W2, W3);                          // 2
    gemm_tc_kernel<<<gemm_blocks, NTHR, GEMM_SMEM>>>(0);            // 3 <- profiled
    sumA_kernel<<<SCAN_BLOCKS, 256>>>();                            // 4
    scanB_kernel<<<1, 256>>>();                                     // 5
    scanC_kernel<<<SCAN_BLOCKS, 256>>>();                           // 6
    fill_kernel<<<(NE + 255) / 256, 256>>>(ei);                     // 7
    agg_kernel<<<agg_blocks, 256>>>(1, b1, nullptr, nullptr);       // 8
    gemm_tc_kernel<<<gemm_blocks, NTHR, GEMM_SMEM>>>(1);            // 9
    agg_kernel<<<agg_blocks, 256>>>(2, b2, b3, out);                // 10
}